// round 2
// baseline (speedup 1.0000x reference)
#include <cuda_runtime.h>
#include <cstdint>
#include <math.h>

// ---------------------------------------------------------------------------
// QuantumLayer: three FFT-diagonal "rotations" collapse into ONE real 64x64
// circulant along the qubit axis. Then amplitude noise (threefry2x32, JAX
// *partitionable* semantics) + per-token L2 norm + abs.
// ---------------------------------------------------------------------------

#define NUM_TOKENS   4096      // B*T
#define HALF_TOKENS  2048
#define DTOT         4096      // Q*d_per
#define HALF_ELEMS   8388608u  // elements of token-b half offset (2048*4096)

__device__ float2 d_gring[128];   // duplicated-lane circulant generator, ring of 128

// ------------------------- threefry2x32 (exact) ----------------------------
__host__ __device__ __forceinline__ unsigned rotl32(unsigned x, int r) {
#if defined(__CUDA_ARCH__)
    return __funnelshift_l(x, x, r);
#else
    return (x << r) | (x >> (32 - r));
#endif
}

__host__ __device__ __forceinline__ void threefry2x32(
    unsigned k0, unsigned k1, unsigned c0, unsigned c1,
    unsigned &y0, unsigned &y1)
{
    unsigned ks2 = k0 ^ k1 ^ 0x1BD11BDAu;
    unsigned x0 = c0 + k0;
    unsigned x1 = c1 + k1;
#define TF_R(r) { x0 += x1; x1 = rotl32(x1, (r)); x1 ^= x0; }
    TF_R(13) TF_R(15) TF_R(26) TF_R(6)
    x0 += k1;  x1 += ks2 + 1u;
    TF_R(17) TF_R(29) TF_R(16) TF_R(24)
    x0 += ks2; x1 += k0 + 2u;
    TF_R(13) TF_R(15) TF_R(26) TF_R(6)
    x0 += k0;  x1 += k1 + 3u;
    TF_R(17) TF_R(29) TF_R(16) TF_R(24)
    x0 += k1;  x1 += ks2 + 4u;
    TF_R(13) TF_R(15) TF_R(26) TF_R(6)
    x0 += ks2; x1 += k0 + 5u;
#undef TF_R
    y0 = x0; y1 = x1;
}

// uniform bits -> N(0,1), matching jax.random.normal (erfinv path).
// Needed absolute accuracy on z is only ~1e-2 (amp = 0.01*z); Giles' poly
// (same family XLA uses) gives ~1e-6.
__device__ __forceinline__ float erfinv_approx(float x)
{
    float w = -__logf(fmaf(-x, x, 1.0f));
    float p;
    if (w < 5.0f) {
        w = w - 2.5f;
        p = 2.81022636e-08f;
        p = fmaf(p, w, 3.43273939e-07f);
        p = fmaf(p, w, -3.5233877e-06f);
        p = fmaf(p, w, -4.39150654e-06f);
        p = fmaf(p, w, 0.00021858087f);
        p = fmaf(p, w, -0.00125372503f);
        p = fmaf(p, w, -0.00417768164f);
        p = fmaf(p, w, 0.246640727f);
        p = fmaf(p, w, 1.50140941f);
    } else {
        w = sqrtf(w) - 3.0f;
        p = -0.000200214257f;
        p = fmaf(p, w, 0.000100950558f);
        p = fmaf(p, w, 0.00134934322f);
        p = fmaf(p, w, -0.00367342844f);
        p = fmaf(p, w, 0.00573950773f);
        p = fmaf(p, w, -0.0076224613f);
        p = fmaf(p, w, 0.00943887047f);
        p = fmaf(p, w, 1.00167406f);
        p = fmaf(p, w, 2.83297682f);
    }
    return p * x;
}

__device__ __forceinline__ float bits_to_normal(unsigned bits)
{
    // u01 in [0,1) from top 23 bits (exactly jax _uniform)
    float f = __uint_as_float((bits >> 9) | 0x3f800000u) - 1.0f;
    // scale to [lo, 1) with lo = nextafterf(-1,0); (hi-lo) rounds to 2.0f in f32
    float u = fmaxf(-0.99999994f, fmaf(f, 2.0f, -0.99999994f));
    return 1.41421354f * erfinv_approx(u);
}

// ------------------------- setup: build generator g ------------------------
// c_axis[m] = (1/64) * sum_f Re(r_f * exp(2*pi*i*f*m/64)); g = cz (*) cy (*) cx
__global__ void setup_kernel(const float* __restrict__ rx,
                             const float* __restrict__ ry,
                             const float* __restrict__ rz)
{
    __shared__ double thx[32], thy[32], thz[32];
    __shared__ double cx[64], cy[64], cz[64], hh[64];
    const int m = threadIdx.x;   // 0..63

    if (m < 32) {
        double sx = 0.0, sy = 0.0, sz = 0.0;
        for (int j = 0; j < 16; j++) {
            sx += (double)rx[m * 16 + j];
            sy += (double)ry[m * 16 + j];
            sz += (double)rz[m * 16 + j];
        }
        thx[m] = 0.5 * sx;
        thy[m] = 0.5 * sy;
        thz[m] = 0.5 * sz;
    }
    __syncthreads();

    const double w = 6.283185307179586476925286766559 / 64.0;
    double ax = 0.0, ay = 0.0, az = 0.0;
    for (int k = 0; k < 32; k++) {
        double p0 = w * (double)(2 * k) * (double)m;
        double p1 = w * (double)(2 * k + 1) * (double)m;
        double c0 = cos(p0), c1 = cos(p1);
        ax += cos(thx[k]) * (c0 + c1);
        ay += cos(thy[k]) * (c0 + c1);
        az += cos(p0 - thz[k]) + cos(p1 + thz[k]);
    }
    cx[m] = ax * (1.0 / 64.0);
    cy[m] = ay * (1.0 / 64.0);
    cz[m] = az * (1.0 / 64.0);
    __syncthreads();

    double acc = 0.0;
    for (int s = 0; s < 64; s++) acc += cy[s] * cx[(m - s) & 63];
    hh[m] = acc;
    __syncthreads();

    double gg = 0.0;
    for (int s = 0; s < 64; s++) gg += cz[s] * hh[(m - s) & 63];
    float gf = (float)gg;
    d_gring[m]      = make_float2(gf, gf);
    d_gring[m + 64] = make_float2(gf, gf);
}

// ------------------------- main kernel -------------------------------------
__device__ __forceinline__ void fma2(unsigned long long &acc,
                                     unsigned long long a,
                                     unsigned long long b)
{
    asm("fma.rn.f32x2 %0, %1, %2, %0;" : "+l"(acc) : "l"(a), "l"(b));
}

__device__ __forceinline__ float2 u2f2(unsigned long long v)
{
    float2 r;
    asm("mov.b64 {%0, %1}, %2;" : "=f"(r.x), "=f"(r.y) : "l"(v));
    return r;
}

__global__ void __launch_bounds__(256, 2)
quantum_main(const float* __restrict__ x, float* __restrict__ out,
             unsigned ka0, unsigned ka1)
{
    __shared__ float4 Xa[1024];   // token a: 64 q-rows x 16 float4
    __shared__ float4 Xb[1024];   // token b
    __shared__ float2 gsh[128];
    __shared__ float redA[8], redB[8];

    const int tid = threadIdx.x;
    const int blk = blockIdx.x;               // token a = blk, token b = blk+2048
    const float4* xa = (const float4*)(x + (size_t)blk * DTOT);
    const float4* xb = (const float4*)(x + (size_t)(blk + HALF_TOKENS) * DTOT);

#pragma unroll
    for (int i = 0; i < 4; i++) {
        Xa[tid + i * 256] = xa[tid + i * 256];
        Xb[tid + i * 256] = xb[tid + i * 256];
    }
    if (tid < 128) gsh[tid] = d_gring[tid];
    __syncthreads();

    const int qg = tid >> 4;      // 0..15 -> q0 = qg*4
    const int dq = tid & 15;      // 0..15 -> d0 = dq*4
    const int q0 = qg << 2;
    const int d0 = dq << 2;

    unsigned long long accA[4][2] = {{0ull,0ull},{0ull,0ull},{0ull,0ull},{0ull,0ull}};
    unsigned long long accB[4][2] = {{0ull,0ull},{0ull,0ull},{0ull,0ull},{0ull,0ull}};

#pragma unroll 8
    for (int p = 0; p < 64; p++) {
        ulonglong2 va = *reinterpret_cast<const ulonglong2*>(&Xa[p * 16 + dq]);
        ulonglong2 vb = *reinterpret_cast<const ulonglong2*>(&Xb[p * 16 + dq]);
        // ring index q0+i-p+64 in [1,127]; gsh[n] == g[n & 63]
        const unsigned long long* grow =
            reinterpret_cast<const unsigned long long*>(&gsh[(q0 + 64) - p]);
#pragma unroll
        for (int i = 0; i < 4; i++) {
            unsigned long long gv = grow[i];
            fma2(accA[i][0], gv, va.x);
            fma2(accA[i][1], gv, va.y);
            fma2(accB[i][0], gv, vb.x);
            fma2(accB[i][1], gv, vb.y);
        }
    }

    // ---- noise (JAX partitionable threefry) + squared sums ----
    // element j (linear index into (B,T,D)) gets counter (hi=0, lo=j);
    // 32 random bits = y0 ^ y1.
    float wa[16], wb[16];
    float sa = 0.0f, sb = 0.0f;
    const unsigned base = (unsigned)blk * (unsigned)DTOT + (unsigned)(q0 * 64 + d0);

#pragma unroll
    for (int i = 0; i < 4; i++) {
        float2 alo = u2f2(accA[i][0]);
        float2 ahi = u2f2(accA[i][1]);
        float2 blo = u2f2(accB[i][0]);
        float2 bhi = u2f2(accB[i][1]);
        float ya4[4] = {alo.x, alo.y, ahi.x, ahi.y};
        float yb4[4] = {blo.x, blo.y, bhi.x, bhi.y};
#pragma unroll
        for (int j = 0; j < 4; j++) {
            unsigned ja = base + (unsigned)(i * 64 + j);
            unsigned jb = ja + HALF_ELEMS;
            unsigned a0, a1, b0, b1;
            threefry2x32(ka0, ka1, 0u, ja, a0, a1);
            threefry2x32(ka0, ka1, 0u, jb, b0, b1);
            float za = bits_to_normal(a0 ^ a1);
            float zb = bits_to_normal(b0 ^ b1);
            float va_ = ya4[j] * fmaf(za, 0.01f, 1.0f);
            float vb_ = yb4[j] * fmaf(zb, 0.01f, 1.0f);
            wa[i * 4 + j] = va_;
            wb[i * 4 + j] = vb_;
            sa = fmaf(va_, va_, sa);
            sb = fmaf(vb_, vb_, sb);
        }
    }

    // ---- block reduction of squared sums (4096 elems per token) ----
#pragma unroll
    for (int off = 16; off > 0; off >>= 1) {
        sa += __shfl_xor_sync(0xffffffffu, sa, off);
        sb += __shfl_xor_sync(0xffffffffu, sb, off);
    }
    const int warp = tid >> 5, lane = tid & 31;
    if (lane == 0) { redA[warp] = sa; redB[warp] = sb; }
    __syncthreads();
    float Sa = 0.0f, Sb = 0.0f;
#pragma unroll
    for (int wd = 0; wd < 8; wd++) { Sa += redA[wd]; Sb += redB[wd]; }
    const float inva = __fdividef(1.0f, sqrtf(Sa) + 1e-8f);
    const float invb = __fdividef(1.0f, sqrtf(Sb) + 1e-8f);

    // ---- write |w| / (norm + 1e-8) ----
    float* oa = out + (size_t)blk * DTOT + (size_t)(q0 * 64 + d0);
    float* ob = out + (size_t)(blk + HALF_TOKENS) * DTOT + (size_t)(q0 * 64 + d0);
#pragma unroll
    for (int i = 0; i < 4; i++) {
        float4 va4, vb4;
        va4.x = fabsf(wa[i * 4 + 0]) * inva;
        va4.y = fabsf(wa[i * 4 + 1]) * inva;
        va4.z = fabsf(wa[i * 4 + 2]) * inva;
        va4.w = fabsf(wa[i * 4 + 3]) * inva;
        vb4.x = fabsf(wb[i * 4 + 0]) * invb;
        vb4.y = fabsf(wb[i * 4 + 1]) * invb;
        vb4.z = fabsf(wb[i * 4 + 2]) * invb;
        vb4.w = fabsf(wb[i * 4 + 3]) * invb;
        *reinterpret_cast<float4*>(oa + i * 64) = va4;
        *reinterpret_cast<float4*>(ob + i * 64) = vb4;
    }
}

// ------------------------- launch ------------------------------------------
extern "C" void kernel_launch(void* const* d_in, const int* in_sizes, int n_in,
                              void* d_out, int out_size)
{
    const float* x  = (const float*)d_in[0];
    const float* rx = (const float*)d_in[1];
    const float* ry = (const float*)d_in[2];
    const float* rz = (const float*)d_in[3];
    float* out = (float*)d_out;

    // Noise key under partitionable threefry:
    // split(key(42)) foldlike: key_i = threefry((0,42), hi=0, lo=i), BOTH words.
    // ka = key_0 (amplitude noise key).
    unsigned ka0, ka1;
    threefry2x32(0u, 42u, 0u, 0u, ka0, ka1);

    setup_kernel<<<1, 64>>>(rx, ry, rz);
    quantum_main<<<HALF_TOKENS, 256>>>(x, out, ka0, ka1);
}

// round 3
// speedup vs baseline: 3.1696x; 3.1696x over previous
#include <cuda_runtime.h>
#include <cstdint>
#include <math.h>

// ---------------------------------------------------------------------------
// QuantumLayer: three FFT-diagonal "rotations" collapse into ONE real 64x64
// circulant along the qubit axis. Then amplitude noise (threefry2x32, JAX
// partitionable semantics) + per-token L2 norm + abs.
// ---------------------------------------------------------------------------

#define NUM_TOKENS   4096      // B*T
#define DTOT         4096      // Q*d_per

__device__ float2 d_gring[128];   // duplicated-lane circulant generator, ring of 128

// ------------------------- threefry2x32 (exact) ----------------------------
__host__ __device__ __forceinline__ unsigned rotl32(unsigned x, int r) {
#if defined(__CUDA_ARCH__)
    return __funnelshift_l(x, x, r);
#else
    return (x << r) | (x >> (32 - r));
#endif
}

__host__ __device__ __forceinline__ void threefry2x32(
    unsigned k0, unsigned k1, unsigned c0, unsigned c1,
    unsigned &y0, unsigned &y1)
{
    unsigned ks2 = k0 ^ k1 ^ 0x1BD11BDAu;
    unsigned x0 = c0 + k0;
    unsigned x1 = c1 + k1;
#define TF_R(r) { x0 += x1; x1 = rotl32(x1, (r)); x1 ^= x0; }
    TF_R(13) TF_R(15) TF_R(26) TF_R(6)
    x0 += k1;  x1 += ks2 + 1u;
    TF_R(17) TF_R(29) TF_R(16) TF_R(24)
    x0 += ks2; x1 += k0 + 2u;
    TF_R(13) TF_R(15) TF_R(26) TF_R(6)
    x0 += k0;  x1 += k1 + 3u;
    TF_R(17) TF_R(29) TF_R(16) TF_R(24)
    x0 += k1;  x1 += ks2 + 4u;
    TF_R(13) TF_R(15) TF_R(26) TF_R(6)
    x0 += ks2; x1 += k0 + 5u;
#undef TF_R
    y0 = x0; y1 = x1;
}

// uniform bits -> N(0,1), matching jax.random.normal (erfinv path).
__device__ __forceinline__ float erfinv_approx(float x)
{
    float w = -__logf(fmaf(-x, x, 1.0f));
    float p;
    if (w < 5.0f) {
        w = w - 2.5f;
        p = 2.81022636e-08f;
        p = fmaf(p, w, 3.43273939e-07f);
        p = fmaf(p, w, -3.5233877e-06f);
        p = fmaf(p, w, -4.39150654e-06f);
        p = fmaf(p, w, 0.00021858087f);
        p = fmaf(p, w, -0.00125372503f);
        p = fmaf(p, w, -0.00417768164f);
        p = fmaf(p, w, 0.246640727f);
        p = fmaf(p, w, 1.50140941f);
    } else {
        w = sqrtf(w) - 3.0f;
        p = -0.000200214257f;
        p = fmaf(p, w, 0.000100950558f);
        p = fmaf(p, w, 0.00134934322f);
        p = fmaf(p, w, -0.00367342844f);
        p = fmaf(p, w, 0.00573950773f);
        p = fmaf(p, w, -0.0076224613f);
        p = fmaf(p, w, 0.00943887047f);
        p = fmaf(p, w, 1.00167406f);
        p = fmaf(p, w, 2.83297682f);
    }
    return p * x;
}

__device__ __forceinline__ float bits_to_normal(unsigned bits)
{
    float f = __uint_as_float((bits >> 9) | 0x3f800000u) - 1.0f;
    float u = fmaxf(-0.99999994f, fmaf(f, 2.0f, -0.99999994f));
    return 1.41421354f * erfinv_approx(u);
}

// ------------------------- setup: build generator g ------------------------
// All phases are 2*pi*(f*m mod 64)/64 -> 64-entry cos/sin tables; the only
// fp64 trig left is cospi/sinpi tables (64) + cos/sin of 96 theta values.
__global__ void setup_kernel(const float* __restrict__ rx,
                             const float* __restrict__ ry,
                             const float* __restrict__ rz)
{
    __shared__ double c64[64], s64[64];
    __shared__ double cthx[32], cthy[32], cthz[32], sthz[32];
    __shared__ double cx[64], cy[64], cz[64], hh[64];
    const int m = threadIdx.x;   // 0..63

    c64[m] = cospi((double)m / 32.0);
    s64[m] = sinpi((double)m / 32.0);

    if (m < 32) {
        double sx = 0.0, sy = 0.0, sz = 0.0;
        for (int j = 0; j < 16; j++) {
            sx += (double)rx[m * 16 + j];
            sy += (double)ry[m * 16 + j];
            sz += (double)rz[m * 16 + j];
        }
        cthx[m] = cos(0.5 * sx);
        cthy[m] = cos(0.5 * sy);
        cthz[m] = cos(0.5 * sz);
        sthz[m] = sin(0.5 * sz);
    }
    __syncthreads();

    double ax = 0.0, ay = 0.0, az = 0.0;
    for (int k = 0; k < 32; k++) {
        int n0 = (2 * k * m) & 63;
        int n1 = ((2 * k + 1) * m) & 63;
        double c0 = c64[n0], c1 = c64[n1];
        double s0 = s64[n0], s1 = s64[n1];
        double cc = c0 + c1;
        ax += cthx[k] * cc;
        ay += cthy[k] * cc;
        // cos(p0 - th) + cos(p1 + th) = cth*(c0+c1) + sth*(s0-s1)
        az += cthz[k] * cc + sthz[k] * (s0 - s1);
    }
    cx[m] = ax * (1.0 / 64.0);
    cy[m] = ay * (1.0 / 64.0);
    cz[m] = az * (1.0 / 64.0);
    __syncthreads();

    double acc = 0.0;
    for (int s = 0; s < 64; s++) acc += cy[s] * cx[(m - s) & 63];
    hh[m] = acc;
    __syncthreads();

    double gg = 0.0;
    for (int s = 0; s < 64; s++) gg += cz[s] * hh[(m - s) & 63];
    float gf = (float)gg;
    d_gring[m]      = make_float2(gf, gf);
    d_gring[m + 64] = make_float2(gf, gf);
}

// ------------------------- main kernel -------------------------------------
__device__ __forceinline__ void fma2(unsigned long long &acc,
                                     unsigned long long a,
                                     unsigned long long b)
{
    asm("fma.rn.f32x2 %0, %1, %2, %0;" : "+l"(acc) : "l"(a), "l"(b));
}

__device__ __forceinline__ float2 u2f2(unsigned long long v)
{
    float2 r;
    asm("mov.b64 {%0, %1}, %2;" : "=f"(r.x), "=f"(r.y) : "l"(v));
    return r;
}

__device__ __forceinline__ void cp_async16(void* smem_dst, const void* gmem_src)
{
    unsigned dst;
    asm("{ .reg .u64 t; cvta.to.shared.u64 t, %1; cvt.u32.u64 %0, t; }"
        : "=r"(dst) : "l"(smem_dst));
    asm volatile("cp.async.ca.shared.global [%0], [%1], 16;" :: "r"(dst), "l"(gmem_src));
}

__global__ void __launch_bounds__(256, 4)
quantum_main(const float* __restrict__ x, float* __restrict__ out,
             unsigned ka0, unsigned ka1)
{
    __shared__ float4 X[1024];      // one token: 64 q-rows x 16 float4 (16KB)
    __shared__ float  noise[4096];  // noise multiplier per element (16KB)
    __shared__ float2 gsh[128];
    __shared__ float  red[8];

    const int tid = threadIdx.x;
    const int blk = blockIdx.x;      // one token per block
    const float4* xs = (const float4*)(x + (size_t)blk * DTOT);

    // Kick off the X tile load; threefry work below hides the DRAM latency.
#pragma unroll
    for (int i = 0; i < 4; i++)
        cp_async16(&X[tid + i * 256], &xs[tid + i * 256]);
    asm volatile("cp.async.commit_group;");

    if (tid < 128) gsh[tid] = d_gring[tid];

    const int qg = tid >> 4;         // q0 = qg*4
    const int dq = tid & 15;         // d0 = dq*4
    const int q0 = qg << 2;
    const int d0 = dq << 2;
    const unsigned base = (unsigned)blk * (unsigned)DTOT + (unsigned)(q0 * 64 + d0);

    // ---- noise multipliers (index-only, overlaps the loads) ----
#pragma unroll
    for (int e = 0; e < 16; e++) {
        unsigned j = base + (unsigned)((e >> 2) * 64 + (e & 3));
        unsigned r0, r1;
        threefry2x32(ka0, ka1, 0u, j, r0, r1);
        float z = bits_to_normal(r0 ^ r1);
        noise[e * 256 + tid] = fmaf(z, 0.01f, 1.0f);
    }

    asm volatile("cp.async.wait_group 0;");
    __syncthreads();

    // ---- circulant matmul along q ----
    unsigned long long acc[4][2] = {{0ull,0ull},{0ull,0ull},{0ull,0ull},{0ull,0ull}};
#pragma unroll 8
    for (int p = 0; p < 64; p++) {
        ulonglong2 v = *reinterpret_cast<const ulonglong2*>(&X[p * 16 + dq]);
        const unsigned long long* grow =
            reinterpret_cast<const unsigned long long*>(&gsh[(q0 + 64) - p]);
#pragma unroll
        for (int i = 0; i < 4; i++) {
            unsigned long long gv = grow[i];
            fma2(acc[i][0], gv, v.x);
            fma2(acc[i][1], gv, v.y);
        }
    }

    // ---- apply noise, accumulate squared sum ----
    float s = 0.0f;
#pragma unroll
    for (int i = 0; i < 4; i++) {
        float2 lo = u2f2(acc[i][0]);
        float2 hi = u2f2(acc[i][1]);
        float w0 = lo.x * noise[(i * 4 + 0) * 256 + tid];
        float w1 = lo.y * noise[(i * 4 + 1) * 256 + tid];
        float w2 = hi.x * noise[(i * 4 + 2) * 256 + tid];
        float w3 = hi.y * noise[(i * 4 + 3) * 256 + tid];
        s = fmaf(w0, w0, s);
        s = fmaf(w1, w1, s);
        s = fmaf(w2, w2, s);
        s = fmaf(w3, w3, s);
    }

    // ---- block reduction (4096 elems per token) ----
#pragma unroll
    for (int off = 16; off > 0; off >>= 1)
        s += __shfl_xor_sync(0xffffffffu, s, off);
    const int warp = tid >> 5, lane = tid & 31;
    if (lane == 0) red[warp] = s;
    __syncthreads();
    float S = 0.0f;
#pragma unroll
    for (int wd = 0; wd < 8; wd++) S += red[wd];
    const float inv = __fdividef(1.0f, sqrtf(S) + 1e-8f);

    // ---- write |y*noise| * inv ----
    float* o = out + (size_t)blk * DTOT + (size_t)(q0 * 64 + d0);
#pragma unroll
    for (int i = 0; i < 4; i++) {
        float2 lo = u2f2(acc[i][0]);
        float2 hi = u2f2(acc[i][1]);
        float4 v;
        v.x = fabsf(lo.x * noise[(i * 4 + 0) * 256 + tid]) * inv;
        v.y = fabsf(lo.y * noise[(i * 4 + 1) * 256 + tid]) * inv;
        v.z = fabsf(hi.x * noise[(i * 4 + 2) * 256 + tid]) * inv;
        v.w = fabsf(hi.y * noise[(i * 4 + 3) * 256 + tid]) * inv;
        *reinterpret_cast<float4*>(o + i * 64) = v;
    }
}

// ------------------------- launch ------------------------------------------
extern "C" void kernel_launch(void* const* d_in, const int* in_sizes, int n_in,
                              void* d_out, int out_size)
{
    const float* x  = (const float*)d_in[0];
    const float* rx = (const float*)d_in[1];
    const float* ry = (const float*)d_in[2];
    const float* rz = (const float*)d_in[3];
    float* out = (float*)d_out;

    // split(key(42)) foldlike: key_0 = threefry((0,42), hi=0, lo=0), both words.
    unsigned ka0, ka1;
    threefry2x32(0u, 42u, 0u, 0u, ka0, ka1);

    setup_kernel<<<1, 64>>>(rx, ry, rz);
    quantum_main<<<NUM_TOKENS, 256>>>(x, out, ka0, ka1);
}

// round 4
// speedup vs baseline: 3.9026x; 1.2313x over previous
#include <cuda_runtime.h>
#include <cstdint>
#include <math.h>

// ---------------------------------------------------------------------------
// QuantumLayer: three FFT-diagonal "rotations" collapse into ONE real 64x64
// circulant along the qubit axis. Then amplitude noise (threefry2x32, JAX
// partitionable semantics) + per-token L2 norm + abs.
// ---------------------------------------------------------------------------

#define NUM_TOKENS   4096      // B*T
#define DTOT         4096      // Q*d_per

// Dual duplicated-lane rings: A[j]=(g[j&63],g[j&63]); B[j]=ring[j+1].
__device__ float2 d_gringA[128];
__device__ float2 d_gringB[128];

// ------------------------- threefry2x32 (exact) ----------------------------
__host__ __device__ __forceinline__ unsigned rotl32(unsigned x, int r) {
#if defined(__CUDA_ARCH__)
    return __funnelshift_l(x, x, r);
#else
    return (x << r) | (x >> (32 - r));
#endif
}

__host__ __device__ __forceinline__ void threefry2x32(
    unsigned k0, unsigned k1, unsigned c0, unsigned c1,
    unsigned &y0, unsigned &y1)
{
    unsigned ks2 = k0 ^ k1 ^ 0x1BD11BDAu;
    unsigned x0 = c0 + k0;
    unsigned x1 = c1 + k1;
#define TF_R(r) { x0 += x1; x1 = rotl32(x1, (r)); x1 ^= x0; }
    TF_R(13) TF_R(15) TF_R(26) TF_R(6)
    x0 += k1;  x1 += ks2 + 1u;
    TF_R(17) TF_R(29) TF_R(16) TF_R(24)
    x0 += ks2; x1 += k0 + 2u;
    TF_R(13) TF_R(15) TF_R(26) TF_R(6)
    x0 += k0;  x1 += k1 + 3u;
    TF_R(17) TF_R(29) TF_R(16) TF_R(24)
    x0 += k1;  x1 += ks2 + 4u;
    TF_R(13) TF_R(15) TF_R(26) TF_R(6)
    x0 += ks2; x1 += k0 + 5u;
#undef TF_R
    y0 = x0; y1 = x1;
}

// uniform bits -> N(0,1), matching jax.random.normal (erfinv path).
__device__ __forceinline__ float erfinv_approx(float x)
{
    float w = -__logf(fmaf(-x, x, 1.0f));
    float p;
    if (w < 5.0f) {
        w = w - 2.5f;
        p = 2.81022636e-08f;
        p = fmaf(p, w, 3.43273939e-07f);
        p = fmaf(p, w, -3.5233877e-06f);
        p = fmaf(p, w, -4.39150654e-06f);
        p = fmaf(p, w, 0.00021858087f);
        p = fmaf(p, w, -0.00125372503f);
        p = fmaf(p, w, -0.00417768164f);
        p = fmaf(p, w, 0.246640727f);
        p = fmaf(p, w, 1.50140941f);
    } else {
        w = sqrtf(w) - 3.0f;
        p = -0.000200214257f;
        p = fmaf(p, w, 0.000100950558f);
        p = fmaf(p, w, 0.00134934322f);
        p = fmaf(p, w, -0.00367342844f);
        p = fmaf(p, w, 0.00573950773f);
        p = fmaf(p, w, -0.0076224613f);
        p = fmaf(p, w, 0.00943887047f);
        p = fmaf(p, w, 1.00167406f);
        p = fmaf(p, w, 2.83297682f);
    }
    return p * x;
}

__device__ __forceinline__ float noise_mult(unsigned ka0, unsigned ka1, unsigned j)
{
    unsigned r0, r1;
    threefry2x32(ka0, ka1, 0u, j, r0, r1);
    unsigned bits = r0 ^ r1;
    float f = __uint_as_float((bits >> 9) | 0x3f800000u) - 1.0f;
    float u = fmaf(f, 2.0f, -0.99999994f);          // in [-0.99999994, ~0.99999988]
    float z = 1.41421354f * erfinv_approx(u);
    return fmaf(z, 0.01f, 1.0f);
}

// ------------------------- setup: build generator g (all fp32) -------------
__global__ void setup_kernel(const float* __restrict__ rx,
                             const float* __restrict__ ry,
                             const float* __restrict__ rz)
{
    __shared__ float c64[64], s64[64];
    __shared__ float cthx[32], cthy[32], cthz[32], sthz[32];
    __shared__ float cx[64], cy[64], cz[64], hh[64], gg[64];
    const int m = threadIdx.x;   // 0..63

    c64[m] = cospif((float)m / 32.0f);
    s64[m] = sinpif((float)m / 32.0f);

    if (m < 32) {
        float sx = 0.0f, sy = 0.0f, sz = 0.0f;
        for (int j = 0; j < 16; j++) {
            sx += rx[m * 16 + j];
            sy += ry[m * 16 + j];
            sz += rz[m * 16 + j];
        }
        cthx[m] = cosf(0.5f * sx);
        cthy[m] = cosf(0.5f * sy);
        cthz[m] = cosf(0.5f * sz);
        sthz[m] = sinf(0.5f * sz);
    }
    __syncthreads();

    float ax = 0.0f, ay = 0.0f, az = 0.0f;
    for (int k = 0; k < 32; k++) {
        int n0 = (2 * k * m) & 63;
        int n1 = ((2 * k + 1) * m) & 63;
        float c0 = c64[n0], c1 = c64[n1];
        float cc = c0 + c1;
        ax = fmaf(cthx[k], cc, ax);
        ay = fmaf(cthy[k], cc, ay);
        // cos(p0 - th) + cos(p1 + th) = cth*(c0+c1) + sth*(s0-s1)
        az = fmaf(cthz[k], cc, fmaf(sthz[k], s64[n0] - s64[n1], az));
    }
    cx[m] = ax * (1.0f / 64.0f);
    cy[m] = ay * (1.0f / 64.0f);
    cz[m] = az * (1.0f / 64.0f);
    __syncthreads();

    float acc = 0.0f;
    for (int s = 0; s < 64; s++) acc = fmaf(cy[s], cx[(m - s) & 63], acc);
    hh[m] = acc;
    __syncthreads();

    float g = 0.0f;
    for (int s = 0; s < 64; s++) g = fmaf(cz[s], hh[(m - s) & 63], g);
    gg[m] = g;
    __syncthreads();

    // rings: A[j] = g[j&63] duplicated; B[j] = g[(j+1)&63] duplicated
    d_gringA[m]      = make_float2(gg[m], gg[m]);
    d_gringA[m + 64] = make_float2(gg[m], gg[m]);
    float gn = gg[(m + 1) & 63];
    d_gringB[m]      = make_float2(gn, gn);
    d_gringB[m + 64] = make_float2(gn, gn);
}

// ------------------------- main kernel -------------------------------------
__device__ __forceinline__ void fma2(unsigned long long &acc,
                                     unsigned long long a,
                                     unsigned long long b)
{
    asm("fma.rn.f32x2 %0, %1, %2, %0;" : "+l"(acc) : "l"(a), "l"(b));
}

__device__ __forceinline__ float2 u2f2(unsigned long long v)
{
    float2 r;
    asm("mov.b64 {%0, %1}, %2;" : "=f"(r.x), "=f"(r.y) : "l"(v));
    return r;
}

__device__ __forceinline__ unsigned long long f2u2(float lo, float hi)
{
    unsigned long long v;
    asm("mov.b64 %0, {%1, %2};" : "=l"(v) : "f"(lo), "f"(hi));
    return v;
}

__device__ __forceinline__ void cp_async16(void* smem_dst, const void* gmem_src)
{
    unsigned dst;
    asm("{ .reg .u64 t; cvta.to.shared.u64 t, %1; cvt.u32.u64 %0, t; }"
        : "=r"(dst) : "l"(smem_dst));
    asm volatile("cp.async.ca.shared.global [%0], [%1], 16;" :: "r"(dst), "l"(gmem_src));
}

__global__ void __launch_bounds__(256, 4)
quantum_main(const float* __restrict__ x, float* __restrict__ out,
             unsigned ka0, unsigned ka1)
{
    __shared__ float4 X[1024];      // one token: 64 q-rows x 16 float4 (16KB)
    __shared__ float2 gshA[128];    // ring A (aligned for even shifts)
    __shared__ float2 gshB[128];    // ring B = A shifted by one pair
    __shared__ float  red[8];

    const int tid = threadIdx.x;
    const int blk = blockIdx.x;      // one token per block
    const float4* xs = (const float4*)(x + (size_t)blk * DTOT);

#pragma unroll
    for (int i = 0; i < 4; i++)
        cp_async16(&X[tid + i * 256], &xs[tid + i * 256]);
    asm volatile("cp.async.commit_group;");

    if (tid < 128)      gshA[tid] = d_gringA[tid];
    else                gshB[tid - 128] = d_gringB[tid - 128];

    const int qg = tid >> 4;         // q0 = qg*4
    const int dq = tid & 15;         // d0 = dq*4
    const int q0 = qg << 2;
    const int d0 = dq << 2;

    asm volatile("cp.async.wait_group 0;");
    __syncthreads();

    // ---- circulant matmul along q (pairs of p; aligned 16B g loads) ----
    unsigned long long acc[4][2] = {{0ull,0ull},{0ull,0ull},{0ull,0ull},{0ull,0ull}};
#pragma unroll 4
    for (int p = 0; p < 64; p += 2) {
        const int r = (q0 + 64) - p;      // even
        // even p: g pairs ring[r..r+3] from A (r even -> 16B aligned)
        ulonglong2 vE  = *reinterpret_cast<const ulonglong2*>(&X[p * 16 + dq]);
        ulonglong2 gE0 = *reinterpret_cast<const ulonglong2*>(&gshA[r]);
        ulonglong2 gE1 = *reinterpret_cast<const ulonglong2*>(&gshA[r + 2]);
        fma2(acc[0][0], gE0.x, vE.x); fma2(acc[0][1], gE0.x, vE.y);
        fma2(acc[1][0], gE0.y, vE.x); fma2(acc[1][1], gE0.y, vE.y);
        fma2(acc[2][0], gE1.x, vE.x); fma2(acc[2][1], gE1.x, vE.y);
        fma2(acc[3][0], gE1.y, vE.x); fma2(acc[3][1], gE1.y, vE.y);
        // odd p+1: need ring[r-1..r+2] = B[r-2..r+1] (r-2 even -> aligned)
        ulonglong2 vO  = *reinterpret_cast<const ulonglong2*>(&X[(p + 1) * 16 + dq]);
        ulonglong2 gO0 = *reinterpret_cast<const ulonglong2*>(&gshB[r - 2]);
        ulonglong2 gO1 = *reinterpret_cast<const ulonglong2*>(&gshB[r]);
        fma2(acc[0][0], gO0.x, vO.x); fma2(acc[0][1], gO0.x, vO.y);
        fma2(acc[1][0], gO0.y, vO.x); fma2(acc[1][1], gO0.y, vO.y);
        fma2(acc[2][0], gO1.x, vO.x); fma2(acc[2][1], gO1.x, vO.y);
        fma2(acc[3][0], gO1.y, vO.x); fma2(acc[3][1], gO1.y, vO.y);
    }

    // ---- noise (threefry per element) applied in-register; squared sum ----
    const unsigned base = (unsigned)blk * (unsigned)DTOT + (unsigned)(q0 * 64 + d0);
    float s = 0.0f;
#pragma unroll
    for (int i = 0; i < 4; i++) {
        float2 lo = u2f2(acc[i][0]);
        float2 hi = u2f2(acc[i][1]);
        const unsigned jb = base + (unsigned)(i * 64);
        float w0 = lo.x * noise_mult(ka0, ka1, jb + 0u);
        float w1 = lo.y * noise_mult(ka0, ka1, jb + 1u);
        float w2 = hi.x * noise_mult(ka0, ka1, jb + 2u);
        float w3 = hi.y * noise_mult(ka0, ka1, jb + 3u);
        s = fmaf(w0, w0, s);
        s = fmaf(w1, w1, s);
        s = fmaf(w2, w2, s);
        s = fmaf(w3, w3, s);
        acc[i][0] = f2u2(w0, w1);        // keep noisy values in the acc regs
        acc[i][1] = f2u2(w2, w3);
    }

    // ---- block reduction (4096 elems per token) ----
#pragma unroll
    for (int off = 16; off > 0; off >>= 1)
        s += __shfl_xor_sync(0xffffffffu, s, off);
    const int warp = tid >> 5, lane = tid & 31;
    if (lane == 0) red[warp] = s;
    __syncthreads();
    float S = 0.0f;
#pragma unroll
    for (int wd = 0; wd < 8; wd++) S += red[wd];
    const float inv = __fdividef(1.0f, sqrtf(S) + 1e-8f);

    // ---- write |w| * inv ----
    float* o = out + (size_t)blk * DTOT + (size_t)(q0 * 64 + d0);
#pragma unroll
    for (int i = 0; i < 4; i++) {
        float2 lo = u2f2(acc[i][0]);
        float2 hi = u2f2(acc[i][1]);
        float4 v;
        v.x = fabsf(lo.x) * inv;
        v.y = fabsf(lo.y) * inv;
        v.z = fabsf(hi.x) * inv;
        v.w = fabsf(hi.y) * inv;
        *reinterpret_cast<float4*>(o + i * 64) = v;
    }
}

// ------------------------- launch ------------------------------------------
extern "C" void kernel_launch(void* const* d_in, const int* in_sizes, int n_in,
                              void* d_out, int out_size)
{
    const float* x  = (const float*)d_in[0];
    const float* rx = (const float*)d_in[1];
    const float* ry = (const float*)d_in[2];
    const float* rz = (const float*)d_in[3];
    float* out = (float*)d_out;

    // split(key(42)) foldlike: key_0 = threefry((0,42), hi=0, lo=0), both words.
    unsigned ka0, ka1;
    threefry2x32(0u, 42u, 0u, 0u, ka0, ka1);

    setup_kernel<<<1, 64>>>(rx, ry, rz);
    quantum_main<<<NUM_TOKENS, 256>>>(x, out, ka0, ka1);
}

// round 6
// speedup vs baseline: 4.0595x; 1.0402x over previous
#include <cuda_runtime.h>
#include <cuda_bf16.h>
#include <cstdint>
#include <math.h>

// ---------------------------------------------------------------------------
// QuantumLayer: three FFT-diagonal rotations = ONE real 64x64 circulant along
// the qubit axis -> bf16-split mma.sync HMMA (tensor pipe, base sm_103 ISA).
// Then amplitude noise (threefry2x32, JAX partitionable) + per-token L2 norm
// + abs on the fma/alu pipes.
// ---------------------------------------------------------------------------

#define DTOT 4096
#define CTAS 2048          // 2 tokens per CTA

// B-fragment table, fragment-register order: [img(hi,lo)][j(8)][kk(4)][lane(32)]
__device__ uint2 d_Bfrag[2048];

// ------------------------- small helpers -----------------------------------
__device__ __forceinline__ unsigned smem_u32(const void* p) {
    unsigned a;
    asm("{ .reg .u64 t; cvta.to.shared.u64 t, %1; cvt.u32.u64 %0, t; }" : "=r"(a) : "l"(p));
    return a;
}
__device__ __forceinline__ void cp_async16(void* s, const void* g) {
    asm volatile("cp.async.ca.shared.global [%0], [%1], 16;" :: "r"(smem_u32(s)), "l"(g));
}
// pack two f32 -> bf16x2, first arg in LOW half
__device__ __forceinline__ unsigned pack_bf16x2(float lo_e, float hi_e) {
    unsigned r;
    asm("cvt.rn.bf16x2.f32 %0, %1, %2;" : "=r"(r) : "f"(hi_e), "f"(lo_e));
    return r;
}
__device__ __forceinline__ void split2(float a, float b, unsigned &hi, unsigned &lo) {
    unsigned h = pack_bf16x2(a, b);
    float ha = __uint_as_float(h << 16);
    float hb = __uint_as_float(h & 0xffff0000u);
    hi = h;
    lo = pack_bf16x2(a - ha, b - hb);
}
#define HMMA(c0,c1,c2,c3,a,b0,b1)                                              \
    asm volatile("mma.sync.aligned.m16n8k16.row.col.f32.bf16.bf16.f32 "        \
        "{%0,%1,%2,%3}, {%4,%5,%6,%7}, {%8,%9}, {%0,%1,%2,%3};"                \
        : "+f"(c0), "+f"(c1), "+f"(c2), "+f"(c3)                               \
        : "r"((a)[0]), "r"((a)[1]), "r"((a)[2]), "r"((a)[3]), "r"(b0), "r"(b1))

// ------------------------- threefry2x32 (exact) ----------------------------
__host__ __device__ __forceinline__ unsigned rotl32(unsigned x, int r) {
#if defined(__CUDA_ARCH__)
    return __funnelshift_l(x, x, r);
#else
    return (x << r) | (x >> (32 - r));
#endif
}
__host__ __device__ __forceinline__ void threefry2x32(
    unsigned k0, unsigned k1, unsigned c0, unsigned c1, unsigned &y0, unsigned &y1)
{
    unsigned ks2 = k0 ^ k1 ^ 0x1BD11BDAu;
    unsigned x0 = c0 + k0;
    unsigned x1 = c1 + k1;
#define TF_R(r) { x0 += x1; x1 = rotl32(x1, (r)); x1 ^= x0; }
    TF_R(13) TF_R(15) TF_R(26) TF_R(6)
    x0 += k1;  x1 += ks2 + 1u;
    TF_R(17) TF_R(29) TF_R(16) TF_R(24)
    x0 += ks2; x1 += k0 + 2u;
    TF_R(13) TF_R(15) TF_R(26) TF_R(6)
    x0 += k0;  x1 += k1 + 3u;
    TF_R(17) TF_R(29) TF_R(16) TF_R(24)
    x0 += k1;  x1 += ks2 + 4u;
    TF_R(13) TF_R(15) TF_R(26) TF_R(6)
    x0 += ks2; x1 += k0 + 5u;
#undef TF_R
    y0 = x0; y1 = x1;
}

__device__ __forceinline__ float erfinv_approx(float x)
{
    float w = -__logf(fmaf(-x, x, 1.0f));
    float p;
    if (w < 5.0f) {
        w = w - 2.5f;
        p = 2.81022636e-08f;
        p = fmaf(p, w, 3.43273939e-07f);
        p = fmaf(p, w, -3.5233877e-06f);
        p = fmaf(p, w, -4.39150654e-06f);
        p = fmaf(p, w, 0.00021858087f);
        p = fmaf(p, w, -0.00125372503f);
        p = fmaf(p, w, -0.00417768164f);
        p = fmaf(p, w, 0.246640727f);
        p = fmaf(p, w, 1.50140941f);
    } else {
        w = sqrtf(w) - 3.0f;
        p = -0.000200214257f;
        p = fmaf(p, w, 0.000100950558f);
        p = fmaf(p, w, 0.00134934322f);
        p = fmaf(p, w, -0.00367342844f);
        p = fmaf(p, w, 0.00573950773f);
        p = fmaf(p, w, -0.0076224613f);
        p = fmaf(p, w, 0.00943887047f);
        p = fmaf(p, w, 1.00167406f);
        p = fmaf(p, w, 2.83297682f);
    }
    return p * x;
}
__device__ __forceinline__ float noise_mult(unsigned ka0, unsigned ka1, unsigned j)
{
    unsigned r0, r1;
    threefry2x32(ka0, ka1, 0u, j, r0, r1);
    unsigned bits = r0 ^ r1;
    float f = __uint_as_float((bits >> 9) | 0x3f800000u) - 1.0f;
    float u = fmaf(f, 2.0f, -0.99999994f);
    float z = 1.41421354f * erfinv_approx(u);
    return fmaf(z, 0.01f, 1.0f);
}

// ------------------------- setup: generator + B-fragment table -------------
__global__ void setup_kernel(const float* __restrict__ rx,
                             const float* __restrict__ ry,
                             const float* __restrict__ rz)
{
    __shared__ float c64[64], s64[64];
    __shared__ float cthx[32], cthy[32], cthz[32], sthz[32];
    __shared__ float cx[64], cy[64], cz[64], hh[64], gg[64];
    const int m = threadIdx.x;   // 0..63

    c64[m] = cospif((float)m / 32.0f);
    s64[m] = sinpif((float)m / 32.0f);
    if (m < 32) {
        float sx = 0.0f, sy = 0.0f, sz = 0.0f;
        for (int j = 0; j < 16; j++) {
            sx += rx[m * 16 + j];
            sy += ry[m * 16 + j];
            sz += rz[m * 16 + j];
        }
        cthx[m] = cosf(0.5f * sx);
        cthy[m] = cosf(0.5f * sy);
        cthz[m] = cosf(0.5f * sz);
        sthz[m] = sinf(0.5f * sz);
    }
    __syncthreads();

    float ax = 0.0f, ay = 0.0f, az = 0.0f;
    for (int k = 0; k < 32; k++) {
        int n0 = (2 * k * m) & 63;
        int n1 = ((2 * k + 1) * m) & 63;
        float cc = c64[n0] + c64[n1];
        ax = fmaf(cthx[k], cc, ax);
        ay = fmaf(cthy[k], cc, ay);
        az = fmaf(cthz[k], cc, fmaf(sthz[k], s64[n0] - s64[n1], az));
    }
    cx[m] = ax * (1.0f / 64.0f);
    cy[m] = ay * (1.0f / 64.0f);
    cz[m] = az * (1.0f / 64.0f);
    __syncthreads();

    float acc = 0.0f;
    for (int s = 0; s < 64; s++) acc = fmaf(cy[s], cx[(m - s) & 63], acc);
    hh[m] = acc;
    __syncthreads();

    float g = 0.0f;
    for (int s = 0; s < 64; s++) g = fmaf(cz[s], hh[(m - s) & 63], g);
    gg[m] = g;
    __syncthreads();

    // B = G^T fragments for mma.m16n8k16.row.col: B[k=p][n=q] = g[(q-p)&63]
    // b0: k = kk*16 + (l&3)*2 + {0,1}, n = j*8 + (l>>2); b1: k += 8.
    for (int e = m; e < 2048; e += 64) {
        int lane = e & 31;
        int kk   = (e >> 5) & 3;
        int j    = (e >> 7) & 7;
        int img  = e >> 10;
        int p0 = kk * 16 + (lane & 3) * 2;
        int q  = j * 8 + (lane >> 2);
        float v0 = gg[(q - p0) & 63];
        float v1 = gg[(q - p0 - 1) & 63];
        float v2 = gg[(q - p0 - 8) & 63];
        float v3 = gg[(q - p0 - 9) & 63];
        unsigned h0, l0, h1, l1;
        split2(v0, v1, h0, l0);
        split2(v2, v3, h1, l1);
        d_Bfrag[e] = (img == 0) ? make_uint2(h0, h1) : make_uint2(l0, l1);
    }
}

// ------------------------- main kernel -------------------------------------
__global__ void __launch_bounds__(256, 2)
quantum_main(const float* __restrict__ x, float* __restrict__ out,
             unsigned ka0, unsigned ka1)
{
    __shared__ __align__(16) uint2 Bf[2048];   // [img][j][kk][lane], 16KB
    __shared__ float red[8];

    const int tid = threadIdx.x;
    const int w   = tid >> 5;
    const int l   = tid & 31;
    const int t   = w >> 2;                   // token within CTA pair
    const int dg  = (w & 3) * 16 + (l >> 2);  // this thread's base d (row)
    const int blk = blockIdx.x;

    // --- async copy of B fragments (64B per thread) ---
#pragma unroll
    for (int i = 0; i < 4; i++)
        cp_async16(&Bf[tid * 8 + i * 2], &d_Bfrag[tid * 8 + i * 2]);
    asm volatile("cp.async.commit_group;");

    // --- A fragments straight from gmem (each byte read once, 4-sector LDGs) ---
    const float* xb = x + (size_t)(2 * blk + t) * DTOT + dg;
    unsigned ahi[4][4], alo[4][4];
#pragma unroll
    for (int kk = 0; kk < 4; kk++) {
        const float* xp = xb + (kk * 16 + (l & 3) * 2) * 64;
        float v00 = xp[0],        v01 = xp[64];         // (d,   k0),(d,   k0+1)
        float v10 = xp[8],        v11 = xp[64 + 8];     // (d+8, k0),(d+8, k0+1)
        float v20 = xp[512],      v21 = xp[576];        // (d,   k0+8),...
        float v30 = xp[512 + 8],  v31 = xp[576 + 8];
        split2(v00, v01, ahi[kk][0], alo[kk][0]);
        split2(v10, v11, ahi[kk][1], alo[kk][1]);
        split2(v20, v21, ahi[kk][2], alo[kk][2]);
        split2(v30, v31, ahi[kk][3], alo[kk][3]);
    }

    asm volatile("cp.async.wait_group 0;");
    __syncthreads();

    // --- 8 n-tiles: 12 HMMAs each (3-term bf16 split), then noise epilogue ---
    float outv[32];
    float s = 0.0f;
    const unsigned jb = (unsigned)((2 * blk + t) * DTOT) + (unsigned)dg;
#pragma unroll
    for (int j = 0; j < 8; j++) {
        float c0 = 0.f, c1 = 0.f, c2 = 0.f, c3 = 0.f;
#pragma unroll
        for (int kk = 0; kk < 4; kk++) {
            uint2 bh = Bf[(j * 4 + kk) * 32 + l];
            uint2 bl = Bf[1024 + (j * 4 + kk) * 32 + l];
            HMMA(c0, c1, c2, c3, ahi[kk], bh.x, bh.y);
            HMMA(c0, c1, c2, c3, alo[kk], bh.x, bh.y);
            HMMA(c0, c1, c2, c3, ahi[kk], bl.x, bl.y);
        }
        const unsigned qe = (unsigned)(j * 8 + (l & 3) * 2);
        float n0 = noise_mult(ka0, ka1, jb + qe * 64u);
        float n1 = noise_mult(ka0, ka1, jb + qe * 64u + 64u);
        float n2 = noise_mult(ka0, ka1, jb + qe * 64u + 8u);
        float n3 = noise_mult(ka0, ka1, jb + qe * 64u + 72u);
        float w0 = c0 * n0, w1 = c1 * n1, w2 = c2 * n2, w3 = c3 * n3;
        s = fmaf(w0, w0, fmaf(w1, w1, fmaf(w2, w2, fmaf(w3, w3, s))));
        outv[j * 4 + 0] = w0;
        outv[j * 4 + 1] = w1;
        outv[j * 4 + 2] = w2;
        outv[j * 4 + 3] = w3;
    }

    // --- per-token norm: warp reduce + 4 warps per token via smem ---
#pragma unroll
    for (int off = 16; off > 0; off >>= 1)
        s += __shfl_xor_sync(0xffffffffu, s, off);
    if (l == 0) red[w] = s;
    __syncthreads();
    const float S = red[t * 4] + red[t * 4 + 1] + red[t * 4 + 2] + red[t * 4 + 3];
    const float inv = __fdividef(1.0f, sqrtf(S) + 1e-8f);

    // --- store |w| * inv ---
    float* o = out + (size_t)(2 * blk + t) * DTOT + dg;
#pragma unroll
    for (int j = 0; j < 8; j++) {
        const int qe = j * 8 + (l & 3) * 2;
        o[qe * 64]        = fabsf(outv[j * 4 + 0]) * inv;
        o[qe * 64 + 64]   = fabsf(outv[j * 4 + 1]) * inv;
        o[qe * 64 + 8]    = fabsf(outv[j * 4 + 2]) * inv;
        o[qe * 64 + 72]   = fabsf(outv[j * 4 + 3]) * inv;
    }
}

// ------------------------- launch ------------------------------------------
extern "C" void kernel_launch(void* const* d_in, const int* in_sizes, int n_in,
                              void* d_out, int out_size)
{
    const float* x  = (const float*)d_in[0];
    const float* rx = (const float*)d_in[1];
    const float* ry = (const float*)d_in[2];
    const float* rz = (const float*)d_in[3];
    float* out = (float*)d_out;

    unsigned ka0, ka1;
    threefry2x32(0u, 42u, 0u, 0u, ka0, ka1);

    setup_kernel<<<1, 64>>>(rx, ry, rz);
    quantum_main<<<CTAS, 256>>>(x, out, ka0, ka1);
}

// round 7
// speedup vs baseline: 4.2254x; 1.0409x over previous
#include <cuda_runtime.h>
#include <cuda_bf16.h>
#include <cstdint>
#include <math.h>

// ---------------------------------------------------------------------------
// QuantumLayer: three FFT-diagonal rotations = ONE real 64x64 circulant along
// the qubit axis -> bf16-split mma.sync HMMA (tensor pipe). Amplitude noise
// (threefry2x32, JAX partitionable) + per-token L2 norm + abs. Noisy values
// round-trip through L2 (stcg/ldcg) instead of living in 32 registers, so
// 4 CTAs/SM fit and the alu pipe can be kept fed.
// ---------------------------------------------------------------------------

#define DTOT 4096
#define CTAS 2048          // 2 tokens per CTA

// B-fragment table, fragment-register order: [img(hi,lo)][j(8)][kk(4)][lane(32)]
__device__ uint2 d_Bfrag[2048];

// ------------------------- small helpers -----------------------------------
__device__ __forceinline__ unsigned smem_u32(const void* p) {
    unsigned a;
    asm("{ .reg .u64 t; cvta.to.shared.u64 t, %1; cvt.u32.u64 %0, t; }" : "=r"(a) : "l"(p));
    return a;
}
__device__ __forceinline__ void cp_async16(void* s, const void* g) {
    asm volatile("cp.async.ca.shared.global [%0], [%1], 16;" :: "r"(smem_u32(s)), "l"(g));
}
// pack two f32 -> bf16x2, first arg in LOW half
__device__ __forceinline__ unsigned pack_bf16x2(float lo_e, float hi_e) {
    unsigned r;
    asm("cvt.rn.bf16x2.f32 %0, %1, %2;" : "=r"(r) : "f"(hi_e), "f"(lo_e));
    return r;
}
__device__ __forceinline__ void split2(float a, float b, unsigned &hi, unsigned &lo) {
    unsigned h = pack_bf16x2(a, b);
    float ha = __uint_as_float(h << 16);
    float hb = __uint_as_float(h & 0xffff0000u);
    hi = h;
    lo = pack_bf16x2(a - ha, b - hb);
}
#define HMMA(c0,c1,c2,c3,a,b0,b1)                                              \
    asm volatile("mma.sync.aligned.m16n8k16.row.col.f32.bf16.bf16.f32 "        \
        "{%0,%1,%2,%3}, {%4,%5,%6,%7}, {%8,%9}, {%0,%1,%2,%3};"                \
        : "+f"(c0), "+f"(c1), "+f"(c2), "+f"(c3)                               \
        : "r"((a)[0]), "r"((a)[1]), "r"((a)[2]), "r"((a)[3]), "r"(b0), "r"(b1))

// ------------------------- threefry2x32 (exact) ----------------------------
__host__ __device__ __forceinline__ unsigned rotl32(unsigned x, int r) {
#if defined(__CUDA_ARCH__)
    return __funnelshift_l(x, x, r);
#else
    return (x << r) | (x >> (32 - r));
#endif
}
__host__ __device__ __forceinline__ void threefry2x32(
    unsigned k0, unsigned k1, unsigned c0, unsigned c1, unsigned &y0, unsigned &y1)
{
    unsigned ks2 = k0 ^ k1 ^ 0x1BD11BDAu;
    unsigned x0 = c0 + k0;
    unsigned x1 = c1 + k1;
#define TF_R(r) { x0 += x1; x1 = rotl32(x1, (r)); x1 ^= x0; }
    TF_R(13) TF_R(15) TF_R(26) TF_R(6)
    x0 += k1;  x1 += ks2 + 1u;
    TF_R(17) TF_R(29) TF_R(16) TF_R(24)
    x0 += ks2; x1 += k0 + 2u;
    TF_R(13) TF_R(15) TF_R(26) TF_R(6)
    x0 += k0;  x1 += k1 + 3u;
    TF_R(17) TF_R(29) TF_R(16) TF_R(24)
    x0 += k1;  x1 += ks2 + 4u;
    TF_R(13) TF_R(15) TF_R(26) TF_R(6)
    x0 += ks2; x1 += k0 + 5u;
#undef TF_R
    y0 = x0; y1 = x1;
}

__device__ __forceinline__ float erfinv_approx(float x)
{
    float w = -__logf(fmaf(-x, x, 1.0f));
    float p;
    if (w < 5.0f) {
        w = w - 2.5f;
        p = 2.81022636e-08f;
        p = fmaf(p, w, 3.43273939e-07f);
        p = fmaf(p, w, -3.5233877e-06f);
        p = fmaf(p, w, -4.39150654e-06f);
        p = fmaf(p, w, 0.00021858087f);
        p = fmaf(p, w, -0.00125372503f);
        p = fmaf(p, w, -0.00417768164f);
        p = fmaf(p, w, 0.246640727f);
        p = fmaf(p, w, 1.50140941f);
    } else {
        w = sqrtf(w) - 3.0f;
        p = -0.000200214257f;
        p = fmaf(p, w, 0.000100950558f);
        p = fmaf(p, w, 0.00134934322f);
        p = fmaf(p, w, -0.00367342844f);
        p = fmaf(p, w, 0.00573950773f);
        p = fmaf(p, w, -0.0076224613f);
        p = fmaf(p, w, 0.00943887047f);
        p = fmaf(p, w, 1.00167406f);
        p = fmaf(p, w, 2.83297682f);
    }
    return p * x;
}
__device__ __forceinline__ float noise_mult(unsigned ka0, unsigned ka1, unsigned j)
{
    unsigned r0, r1;
    threefry2x32(ka0, ka1, 0u, j, r0, r1);
    unsigned bits = r0 ^ r1;
    float f = __uint_as_float((bits >> 9) | 0x3f800000u) - 1.0f;
    float u = fmaf(f, 2.0f, -0.99999994f);
    float z = 1.41421354f * erfinv_approx(u);
    return fmaf(z, 0.01f, 1.0f);
}

// ------------------------- setup: generator + B-fragment table -------------
__global__ void setup_kernel(const float* __restrict__ rx,
                             const float* __restrict__ ry,
                             const float* __restrict__ rz)
{
    __shared__ float c64[64], s64[64];
    __shared__ float cthx[32], cthy[32], cthz[32], sthz[32];
    __shared__ float cx[64], cy[64], cz[64], hh[64], gg[64];
    const int tid = threadIdx.x;   // 0..255
    const int m = tid;

    if (m < 64) {
        c64[m] = cospif((float)m / 32.0f);
        s64[m] = sinpif((float)m / 32.0f);
    }
    if (m < 32) {
        float sx = 0.0f, sy = 0.0f, sz = 0.0f;
        for (int j = 0; j < 16; j++) {
            sx += rx[m * 16 + j];
            sy += ry[m * 16 + j];
            sz += rz[m * 16 + j];
        }
        cthx[m] = cosf(0.5f * sx);
        cthy[m] = cosf(0.5f * sy);
        cthz[m] = cosf(0.5f * sz);
        sthz[m] = sinf(0.5f * sz);
    }
    __syncthreads();

    if (m < 64) {
        float ax = 0.0f, ay = 0.0f, az = 0.0f;
        for (int k = 0; k < 32; k++) {
            int n0 = (2 * k * m) & 63;
            int n1 = ((2 * k + 1) * m) & 63;
            float cc = c64[n0] + c64[n1];
            ax = fmaf(cthx[k], cc, ax);
            ay = fmaf(cthy[k], cc, ay);
            az = fmaf(cthz[k], cc, fmaf(sthz[k], s64[n0] - s64[n1], az));
        }
        cx[m] = ax * (1.0f / 64.0f);
        cy[m] = ay * (1.0f / 64.0f);
        cz[m] = az * (1.0f / 64.0f);
    }
    __syncthreads();

    if (m < 64) {
        float acc = 0.0f;
        for (int s = 0; s < 64; s++) acc = fmaf(cy[s], cx[(m - s) & 63], acc);
        hh[m] = acc;
    }
    __syncthreads();

    if (m < 64) {
        float g = 0.0f;
        for (int s = 0; s < 64; s++) g = fmaf(cz[s], hh[(m - s) & 63], g);
        gg[m] = g;
    }
    __syncthreads();

    // B = G^T fragments for mma.m16n8k16.row.col: B[k=p][n=q] = g[(q-p)&63]
    for (int e = tid; e < 2048; e += 256) {
        int lane = e & 31;
        int kk   = (e >> 5) & 3;
        int j    = (e >> 7) & 7;
        int img  = e >> 10;
        int p0 = kk * 16 + (lane & 3) * 2;
        int q  = j * 8 + (lane >> 2);
        float v0 = gg[(q - p0) & 63];
        float v1 = gg[(q - p0 - 1) & 63];
        float v2 = gg[(q - p0 - 8) & 63];
        float v3 = gg[(q - p0 - 9) & 63];
        unsigned h0, l0, h1, l1;
        split2(v0, v1, h0, l0);
        split2(v2, v3, h1, l1);
        d_Bfrag[e] = (img == 0) ? make_uint2(h0, h1) : make_uint2(l0, l1);
    }
}

// ------------------------- main kernel -------------------------------------
__global__ void __launch_bounds__(256, 4)
quantum_main(const float* __restrict__ x, float* __restrict__ out,
             unsigned ka0, unsigned ka1)
{
    __shared__ __align__(16) uint2 Bf[2048];   // [img][j][kk][lane], 16KB
    __shared__ float red[8];

    const int tid = threadIdx.x;
    const int w   = tid >> 5;
    const int l   = tid & 31;
    const int t   = w >> 2;                   // token within CTA pair
    const int dg  = (w & 3) * 16 + (l >> 2);  // this thread's base d (row)
    const int blk = blockIdx.x;

    // --- async copy of B fragments (64B per thread) ---
#pragma unroll
    for (int i = 0; i < 4; i++)
        cp_async16(&Bf[tid * 8 + i * 2], &d_Bfrag[tid * 8 + i * 2]);
    asm volatile("cp.async.commit_group;");

    // --- A fragments straight from gmem (each byte read once, 4-sector LDGs) ---
    const float* xb = x + (size_t)(2 * blk + t) * DTOT + dg;
    unsigned ahi[4][4], alo[4][4];
#pragma unroll
    for (int kk = 0; kk < 4; kk++) {
        const float* xp = xb + (kk * 16 + (l & 3) * 2) * 64;
        float v00 = xp[0],        v01 = xp[64];
        float v10 = xp[8],        v11 = xp[64 + 8];
        float v20 = xp[512],      v21 = xp[576];
        float v30 = xp[512 + 8],  v31 = xp[576 + 8];
        split2(v00, v01, ahi[kk][0], alo[kk][0]);
        split2(v10, v11, ahi[kk][1], alo[kk][1]);
        split2(v20, v21, ahi[kk][2], alo[kk][2]);
        split2(v30, v31, ahi[kk][3], alo[kk][3]);
    }

    asm volatile("cp.async.wait_group 0;");
    __syncthreads();

    // --- 8 n-tiles: 12 HMMAs (3-term bf16 split); noisy values -> L2 (stcg) ---
    float s = 0.0f;
    const unsigned jb = (unsigned)((2 * blk + t) * DTOT) + (unsigned)dg;
    float* o = out + (size_t)(2 * blk + t) * DTOT + dg;
#pragma unroll
    for (int j = 0; j < 8; j++) {
        float c0 = 0.f, c1 = 0.f, c2 = 0.f, c3 = 0.f;
#pragma unroll
        for (int kk = 0; kk < 4; kk++) {
            uint2 bh = Bf[(j * 4 + kk) * 32 + l];
            uint2 bl = Bf[1024 + (j * 4 + kk) * 32 + l];
            HMMA(c0, c1, c2, c3, ahi[kk], bh.x, bh.y);
            HMMA(c0, c1, c2, c3, alo[kk], bh.x, bh.y);
            HMMA(c0, c1, c2, c3, ahi[kk], bl.x, bl.y);
        }
        const unsigned qe = (unsigned)(j * 8 + (l & 3) * 2);
        float n0 = noise_mult(ka0, ka1, jb + qe * 64u);
        float n1 = noise_mult(ka0, ka1, jb + qe * 64u + 64u);
        float n2 = noise_mult(ka0, ka1, jb + qe * 64u + 8u);
        float n3 = noise_mult(ka0, ka1, jb + qe * 64u + 72u);
        float w0 = c0 * n0, w1 = c1 * n1, w2 = c2 * n2, w3 = c3 * n3;
        s = fmaf(w0, w0, fmaf(w1, w1, fmaf(w2, w2, fmaf(w3, w3, s))));
        float* oj = o + qe * 64;
        __stcg(oj,      w0);
        __stcg(oj + 64, w1);
        __stcg(oj + 8,  w2);
        __stcg(oj + 72, w3);
    }

    // --- per-token norm: warp reduce + 4 warps per token via smem ---
#pragma unroll
    for (int off = 16; off > 0; off >>= 1)
        s += __shfl_xor_sync(0xffffffffu, s, off);
    if (l == 0) red[w] = s;
    __syncthreads();
    const float S = red[t * 4] + red[t * 4 + 1] + red[t * 4 + 2] + red[t * 4 + 3];
    const float inv = __fdividef(1.0f, sqrtf(S) + 1e-8f);

    // --- read back own values from L2, finalize |w| * inv ---
#pragma unroll
    for (int j = 0; j < 8; j++) {
        const int qe = j * 8 + (l & 3) * 2;
        float* oj = o + qe * 64;
        float w0 = __ldcg(oj);
        float w1 = __ldcg(oj + 64);
        float w2 = __ldcg(oj + 8);
        float w3 = __ldcg(oj + 72);
        __stcg(oj,      fabsf(w0) * inv);
        __stcg(oj + 64, fabsf(w1) * inv);
        __stcg(oj + 8,  fabsf(w2) * inv);
        __stcg(oj + 72, fabsf(w3) * inv);
    }
}

// ------------------------- launch ------------------------------------------
extern "C" void kernel_launch(void* const* d_in, const int* in_sizes, int n_in,
                              void* d_out, int out_size)
{
    const float* x  = (const float*)d_in[0];
    const float* rx = (const float*)d_in[1];
    const float* ry = (const float*)d_in[2];
    const float* rz = (const float*)d_in[3];
    float* out = (float*)d_out;

    unsigned ka0, ka1;
    threefry2x32(0u, 42u, 0u, 0u, ka0, ka1);

    setup_kernel<<<1, 256>>>(rx, ry, rz);
    quantum_main<<<CTAS, 256>>>(x, out, ka0, ka1);
}